// round 17
// baseline (speedup 1.0000x reference)
#include <cuda_runtime.h>
#include <math.h>
#include <limits.h>

#define BATCH 4096
#define DIM   512
#define NCLS  128
#define BPC   2                   // blocks per class -> 256 blocks = one wave @2 CTA/SM
#define NBLK  (NCLS * BPC)
#define THR   256
#define MAXM  128                 // member list cap
#define STAGE 52                  // rows staged in dynamic smem (52*2KB = 104KB)
#define STAGE_BYTES (STAGE * DIM * 4)
#define AW    2                   // anchors per warp

__device__ double g_partial[NBLK];
__device__ int    g_pcount[NBLK];
__device__ int    g_done;

__device__ __forceinline__ float wsum32(float v) {
    #pragma unroll
    for (int o = 16; o; o >>= 1) v += __shfl_xor_sync(0xFFFFFFFFu, v, o);
    return v;
}

__global__ void __launch_bounds__(THR, 2) k_main(
    const float* __restrict__ batch,
    const int*   __restrict__ labels,
    const int*   __restrict__ anchors,
    const int*   __restrict__ negatives,
    float*       __restrict__ out)
{
    extern __shared__ __align__(16) float sh_tile[];   // STAGE rows x DIM floats

    const int c    = blockIdx.x >> 1;
    const int half = blockIdx.x & 1;
    const int tid  = threadIdx.x;
    const int lane = tid & 31;
    const int wid  = tid >> 5;              // 0..7
    const int slot = half * 8 + wid;        // 0..15 warp slot within class

    __shared__ int    sh_raw[MAXM];
    __shared__ int    sh_memb[MAXM];        // rank-sorted: canonical across sibling blocks
    __shared__ double sh_ws[8];
    __shared__ int    sh_wc[8];
    __shared__ int    sh_cnt, sh_last;

    // ---- build member list ----
    if (tid == 0) sh_cnt = 0;
    __syncthreads();
    for (int s = tid; s < BATCH; s += THR) {
        if (labels[s] == c) {
            int pos = atomicAdd(&sh_cnt, 1);
            if (pos < MAXM) sh_raw[pos] = s;
        }
    }
    __syncthreads();
    const int cnt = min(sh_cnt, MAXM);

    // ---- rank-sort ascending: canonical anchor partition across the 2 blocks ----
    for (int t = tid; t < cnt; t += THR) {
        int v = sh_raw[t];
        int rank = 0;
        for (int k = 0; k < cnt; ++k) rank += (sh_raw[k] < v);
        sh_memb[rank] = v;
    }
    __syncthreads();

    // ---- stage member rows into smem (one shot, one barrier) ----
    const int nst = min(cnt, STAGE);
    {
        float4* dst = (float4*)sh_tile;
        for (int idx = tid; idx < nst * (DIM / 4); idx += THR) {
            int row = idx >> 7, sub = idx & 127;       // DIM/4 = 128 float4 per row
            dst[row * (DIM / 4) + sub] =
                ((const float4*)(batch + (size_t)sh_memb[row] * DIM))[sub];
        }
    }
    __syncthreads();                                   // last barrier before mainloop

    double wsum = 0.0;
    int    wcnt = 0;

    if (cnt >= 3) {                                    // valid iff (cnt-1) > 1
        for (int base = slot * AW; base < cnt; base += 16 * AW) {
            const int  am0 = sh_memb[base];
            const bool v1  = (base + 1 < cnt);
            const int  am1 = v1 ? sh_memb[base + 1] : -1;

            // a2 = 2*anchor_row (key = sum b*(b-2a)); a recovered exactly as 0.5*a2
            float a20[16], a21[16];
            {
                const float* s0 = (base < nst) ? &sh_tile[(size_t)base * DIM]
                                               : (batch + (size_t)am0 * DIM);
                const int  i1   = v1 ? base + 1 : base;
                const float* s1 = (i1 < nst) ? &sh_tile[(size_t)i1 * DIM]
                                             : (batch + (size_t)sh_memb[i1] * DIM);
                #pragma unroll
                for (int k = 0; k < 4; ++k) {
                    float4 v = ((const float4*)s0)[lane + 32 * k];
                    a20[4*k+0] = 2.f*v.x; a20[4*k+1] = 2.f*v.y;
                    a20[4*k+2] = 2.f*v.z; a20[4*k+3] = 2.f*v.w;
                    float4 w = ((const float4*)s1)[lane + 32 * k];
                    a21[4*k+0] = 2.f*w.x; a21[4*k+1] = 2.f*w.y;
                    a21[4*k+2] = 2.f*w.z; a21[4*k+3] = 2.f*w.w;
                }
            }

            float bk0 = INFINITY, bk1 = INFINITY;
            int   bj0 = INT_MAX,  bj1 = INT_MAX;

            for (int m = 0; m < cnt; ++m) {
                const int j = sh_memb[m];
                const float4* rp = (m < nst)
                    ? (const float4*)&sh_tile[(size_t)m * DIM]
                    : (const float4*)(batch + (size_t)j * DIM);
                float k0 = 0.f, k1 = 0.f;
                #pragma unroll
                for (int k4 = 0; k4 < 4; ++k4) {
                    float4 v = rp[lane + 32 * k4];
                    k0 = fmaf(v.x, v.x - a20[4*k4+0], k0);
                    k0 = fmaf(v.y, v.y - a20[4*k4+1], k0);
                    k0 = fmaf(v.z, v.z - a20[4*k4+2], k0);
                    k0 = fmaf(v.w, v.w - a20[4*k4+3], k0);
                    k1 = fmaf(v.x, v.x - a21[4*k4+0], k1);
                    k1 = fmaf(v.y, v.y - a21[4*k4+1], k1);
                    k1 = fmaf(v.z, v.z - a21[4*k4+2], k1);
                    k1 = fmaf(v.w, v.w - a21[4*k4+3], k1);
                }
                #pragma unroll
                for (int o = 16; o; o >>= 1) {
                    k0 += __shfl_xor_sync(0xFFFFFFFFu, k0, o);
                    k1 += __shfl_xor_sync(0xFFFFFFFFu, k1, o);
                }
                if (j != am0 && (k0 < bk0 || (k0 == bk0 && j < bj0))) { bk0 = k0; bj0 = j; }
                if (v1 && j != am1 && (k1 < bk1 || (k1 == bk1 && j < bj1))) { bk1 = k1; bj1 = j; }
            }

            // ---- epilogue: d_ap, d_an via direct diff (matches _pair_dist) ----
            #pragma unroll
            for (int r = 0; r < AW; ++r) {
                if (r == 1 && !v1) break;
                const int   t_  = (r == 0) ? am0 : am1;
                const int   p   = (r == 0) ? bj0 : bj1;
                const float* a2 = (r == 0) ? a20 : a21;
                const int   a    = anchors[t_];
                const int   nidx = negatives[t_];
                const float4* pp = (const float4*)(batch + (size_t)p * DIM);
                const float4* np = (const float4*)(batch + (size_t)nidx * DIM);
                float s1 = 0.f, s2 = 0.f;
                if (a == t_) {
                    #pragma unroll
                    for (int k = 0; k < 4; ++k) {
                        float4 pv = pp[lane + 32 * k], nv = np[lane + 32 * k];
                        float va0 = 0.5f*a2[4*k+0], va1 = 0.5f*a2[4*k+1];
                        float va2 = 0.5f*a2[4*k+2], va3 = 0.5f*a2[4*k+3];
                        float e;
                        e = va0 - pv.x; s1 = fmaf(e,e,s1); e = va0 - nv.x; s2 = fmaf(e,e,s2);
                        e = va1 - pv.y; s1 = fmaf(e,e,s1); e = va1 - nv.y; s2 = fmaf(e,e,s2);
                        e = va2 - pv.z; s1 = fmaf(e,e,s1); e = va2 - nv.z; s2 = fmaf(e,e,s2);
                        e = va3 - pv.w; s1 = fmaf(e,e,s1); e = va3 - nv.w; s2 = fmaf(e,e,s2);
                    }
                } else {   // general path (kept for correctness)
                    const float4* ap = (const float4*)(batch + (size_t)a * DIM);
                    #pragma unroll
                    for (int k = 0; k < 4; ++k) {
                        float4 av = ap[lane + 32 * k], pv = pp[lane + 32 * k], nv = np[lane + 32 * k];
                        float e;
                        e = av.x - pv.x; s1 = fmaf(e,e,s1); e = av.x - nv.x; s2 = fmaf(e,e,s2);
                        e = av.y - pv.y; s1 = fmaf(e,e,s1); e = av.y - nv.y; s2 = fmaf(e,e,s2);
                        e = av.z - pv.z; s1 = fmaf(e,e,s1); e = av.z - nv.z; s2 = fmaf(e,e,s2);
                        e = av.w - pv.w; s1 = fmaf(e,e,s1); e = av.w - nv.w; s2 = fmaf(e,e,s2);
                    }
                }
                s1 = wsum32(s1); s2 = wsum32(s2);
                if (lane == 0) {
                    float d_ap = sqrtf(fmaxf(s1, 1e-12f));
                    float d_an = sqrtf(fmaxf(s2, 1e-12f));
                    float x    = (d_ap - d_an) * 10.f;      // (s_an-s_ap)/TEMP
                    float per  = fmaxf(x, 0.f) + log1pf(expf(-fabsf(x)));
                    wsum += (double)per; wcnt += 1;
                }
            }
        }
    }

    if (lane == 0) { sh_ws[wid] = wsum; sh_wc[wid] = wcnt; }
    __syncthreads();
    if (tid == 0) {
        double s = 0.0; int n = 0;
        #pragma unroll
        for (int w = 0; w < 8; ++w) { s += sh_ws[w]; n += sh_wc[w]; }
        g_partial[blockIdx.x] = s;
        g_pcount[blockIdx.x]  = n;
        __threadfence();
        int old = atomicAdd(&g_done, 1);
        sh_last = (old == NBLK - 1);
    }
    __syncthreads();

    // ---- last block reduces all partials (single launch) ----
    if (sh_last) {
        double s = 0.0; int n = 0;
        for (int t2 = tid; t2 < NBLK; t2 += THR) { s += g_partial[t2]; n += g_pcount[t2]; }
        #pragma unroll
        for (int o = 16; o; o >>= 1) {
            s += __shfl_xor_sync(0xFFFFFFFFu, s, o);
            n += __shfl_xor_sync(0xFFFFFFFFu, n, o);
        }
        if (lane == 0) { sh_ws[wid] = s; sh_wc[wid] = n; }
        __syncthreads();
        if (tid == 0) {
            double ts = 0.0; int tn = 0;
            #pragma unroll
            for (int w = 0; w < 8; ++w) { ts += sh_ws[w]; tn += sh_wc[w]; }
            out[0] = (float)(ts / (double)tn);
            g_done = 0;   // reset for next graph replay
        }
    }
}

extern "C" void kernel_launch(void* const* d_in, const int* in_sizes, int n_in,
                              void* d_out, int out_size) {
    const float* batch     = (const float*)d_in[0];
    const int*   labels    = (const int*)d_in[1];
    const int*   anchors   = (const int*)d_in[2];
    const int*   negatives = (const int*)d_in[3];
    float* out = (float*)d_out;

    cudaFuncSetAttribute(k_main, cudaFuncAttributeMaxDynamicSharedMemorySize, STAGE_BYTES);
    k_main<<<NBLK, THR, STAGE_BYTES>>>(batch, labels, anchors, negatives, out);
}